// round 5
// baseline (speedup 1.0000x reference)
#include <cuda_runtime.h>

// Fixed shape: depthin (1,1,480,640) float32 -> scalar float32.
#define ROWS 480
#define COLS 640
#define TH   8
#define TW   32
#define NT   (TH * TW)    // 256
#define S    7
#define P    3
#define SMH  (TH + 2*P)   // 14
#define SMW  (TW + 2*P)   // 38
#define NBX  (COLS / TW)  // 20
#define NBY  (ROWS / TH)  // 60
#define NB   (NBX * NBY)  // 1200

__device__ float g_blocksums[NB];
__device__ unsigned int g_count = 0;

typedef unsigned long long u64;

__device__ __forceinline__ float fsqrt_approx(float x) {
    float r;
    asm("sqrt.approx.f32 %0, %1;" : "=f"(r) : "f"(x));
    return r;
}
__device__ __forceinline__ u64 pack2(float lo, float hi) {
    u64 r; asm("mov.b64 %0, {%1, %2};" : "=l"(r) : "f"(lo), "f"(hi)); return r;
}
__device__ __forceinline__ void unpack2(u64 v, float& lo, float& hi) {
    asm("mov.b64 {%0, %1}, %2;" : "=f"(lo), "=f"(hi) : "l"(v));
}
__device__ __forceinline__ u64 fma2(u64 a, u64 b, u64 c) {
    u64 d; asm("fma.rn.f32x2 %0, %1, %2, %3;" : "=l"(d) : "l"(a), "l"(b), "l"(c)); return d;
}
__device__ __forceinline__ u64 mul2(u64 a, u64 b) {
    u64 d; asm("mul.rn.f32x2 %0, %1, %2;" : "=l"(d) : "l"(a), "l"(b)); return d;
}
__device__ __forceinline__ u64 add2(u64 a, u64 b) {
    u64 d; asm("add.rn.f32x2 %0, %1, %2;" : "=l"(d) : "l"(a), "l"(b)); return d;
}

__device__ __forceinline__ float load_z(const float* __restrict__ depth, int gr, int gc) {
    gr = min(max(gr, 0), ROWS - 1);
    gc = min(max(gc, 0), COLS - 1);
    float d = __ldg(&depth[gr * COLS + gc]);
    return (d > 0.0f && d < 1.01f) ? d * 1e-3f : 0.0f;
}

__global__ __launch_bounds__(NT)
void stdev_fused_kernel(const float* __restrict__ depth, float* __restrict__ out) {
    // Two parity-shifted copies of the z tile so every thread's column-pairs
    // are 8-byte-aligned LDS.64 regardless of smc0 parity.
    __shared__ __align__(16) float szA[SMH][SMW];  // col c -> global bj0 - P + c
    __shared__ __align__(16) float szB[SMH][SMW];  // col c -> global bj0 - P + c + 1
    __shared__ float wsum[NT / 32];
    __shared__ int   is_last;

    const float inv_fx = (float)(1.0 / 582.6244816773795);
    const float inv_fy = (float)(1.0 / 582.6910327098864);
    const float cx = 313.0447587080473f;
    const float cy = 238.44389626620386f;

    const int bj0 = blockIdx.x * TW;
    const int bi0 = blockIdx.y * TH;
    const int tid = threadIdx.y * TW + threadIdx.x;
    const int bid = blockIdx.y * NBX + blockIdx.x;

    #pragma unroll
    for (int idx = tid; idx < SMH * SMW; idx += NT) {
        int lr = idx / SMW, lc = idx % SMW;
        int gr = bi0 + lr - P;
        int gc = bj0 + lc - P;
        szA[lr][lc] = load_z(depth, gr, gc);
        szB[lr][lc] = load_z(depth, gr, gc + 1);
    }
    __syncthreads();

    const int i = bi0 + threadIdx.y;
    const int j = bj0 + threadIdx.x;

    // Clamped window start (matches reference idif/jdif boundary shift).
    const int istart = min(max(i - P, 0), ROWS - S);
    const int jstart = min(max(j - P, 0), COLS - S);
    const int smr0 = istart - bi0 + P;   // in [0, SMH-S]
    const int smc0 = jstart - bj0 + P;   // in [0, SMW-S]

    const float z0 = szA[threadIdx.y + P][threadIdx.x + P];
    const float x0 = z0 * (((float)j - cx) * inv_fx);
    const float y0 = z0 * (((float)i - cy) * inv_fy);

    float negcs[S], negrs[S];
    #pragma unroll
    for (int t = 0; t < S; t++) negcs[t] = -(((float)(jstart + t) - cx) * inv_fx);
    #pragma unroll
    for (int s = 0; s < S; s++) negrs[s] = -(((float)(istart + s) - cy) * inv_fy);

    u64 negcs2[3];
    negcs2[0] = pack2(negcs[0], negcs[1]);
    negcs2[1] = pack2(negcs[2], negcs[3]);
    negcs2[2] = pack2(negcs[4], negcs[5]);

    const u64 x02 = pack2(x0, x0);
    const u64 y02 = pack2(y0, y0);
    const u64 z02 = pack2(z0, z0);
    const u64 cm1 = pack2(-1.0f, -1.0f);

    // Parity select: pair loads come from szA (even smc0) or szB (odd smc0),
    // at an even (8B-aligned) column base.
    const bool odd = (smc0 & 1);
    const int cb = odd ? (smc0 - 1) : smc0;
    const float* tileP = odd ? &szB[0][0] : &szA[0][0];

    u64 sumsq2 = pack2(0.0f, 0.0f);
    float sumd_a = 0.0f, sumd_b = 0.0f;
    float sumsq1 = 0.0f, sumd1 = 0.0f;

    #pragma unroll
    for (int s = 0; s < S; s++) {
        const int r = smr0 + s;
        const u64* prow = (const u64*)(tileP + r * SMW + cb);   // 8B-aligned
        const u64 negrs2 = pack2(negrs[s], negrs[s]);

        #pragma unroll
        for (int p = 0; p < 3; p++) {
            u64 zn2 = prow[p];                       // LDS.64, no packing
            u64 dz2 = fma2(zn2, cm1, z02);           // z0 - zn
            u64 dx2 = fma2(zn2, negcs2[p], x02);     // x0 - zn*cs
            u64 dy2 = fma2(zn2, negrs2, y02);        // y0 - zn*rs
            u64 m   = mul2(dz2, dz2);
            m       = fma2(dy2, dy2, m);
            u64 sq2 = fma2(dx2, dx2, m);
            sumsq2  = add2(sumsq2, sq2);
            float q0, q1; unpack2(sq2, q0, q1);      // register pair, no data move
            sumd_a += fsqrt_approx(q0);
            sumd_b += fsqrt_approx(q1);
        }
        // remainder column t=6 (scalar, from unshifted tile)
        {
            float zn = szA[r][smc0 + 6];
            float dz = z0 - zn;
            float dx = fmaf(zn, negcs[6], x0);
            float dy = fmaf(zn, negrs[s], y0);
            float sq = fmaf(dx, dx, fmaf(dy, dy, dz * dz));
            sumsq1 += sq;
            sumd1  += fsqrt_approx(sq);
        }
    }

    float ssl, ssh;
    unpack2(sumsq2, ssl, ssh);
    const float sumd  = sumd_a + sumd_b + sumd1;
    const float sumsq = ssl + ssh + sumsq1;

    float var = (sumsq - sumd * sumd * (1.0f / 49.0f)) * (1.0f / 48.0f);
    float dev = (z0 > 0.0f) ? sqrtf(fmaxf(var, 0.0f)) : 0.0f;

    // Deterministic block reduction.
    float v = dev;
    #pragma unroll
    for (int o = 16; o; o >>= 1) v += __shfl_xor_sync(0xffffffffu, v, o);
    if ((tid & 31) == 0) wsum[tid >> 5] = v;
    __syncthreads();

    if (tid < 8) {
        float w = wsum[tid];
        #pragma unroll
        for (int o = 4; o; o >>= 1) w += __shfl_xor_sync(0x000000ffu, w, o, 8);
        if (tid == 0) {
            g_blocksums[bid] = w;
            __threadfence();
            unsigned int cnt = atomicAdd(&g_count, 1u);
            is_last = (cnt == NB - 1);
        }
    }
    __syncthreads();

    // Last block folds the fixed 1200-slot array (fixed order -> deterministic).
    if (is_last) {
        __threadfence();
        float srun = 0.0f;
        for (int idx = tid; idx < NB; idx += NT)
            srun += ((volatile float*)g_blocksums)[idx];
        #pragma unroll
        for (int o = 16; o; o >>= 1) srun += __shfl_xor_sync(0xffffffffu, srun, o);
        if ((tid & 31) == 0) wsum[tid >> 5] = srun;
        __syncthreads();
        if (tid < 8) {
            float w = wsum[tid];
            #pragma unroll
            for (int o = 4; o; o >>= 1) w += __shfl_xor_sync(0x000000ffu, w, o, 8);
            if (tid == 0) {
                out[0] = w * 100.0f;
                g_count = 0;   // re-arm for next graph replay
            }
        }
    }
}

extern "C" void kernel_launch(void* const* d_in, const int* in_sizes, int n_in,
                              void* d_out, int out_size) {
    const float* depth = (const float*)d_in[0];   // depthin (1,1,480,640)
    float* out = (float*)d_out;
    dim3 grid(NBX, NBY);
    dim3 block(TW, TH);
    stdev_fused_kernel<<<grid, block>>>(depth, out);
}

// round 6
// speedup vs baseline: 1.0194x; 1.0194x over previous
#include <cuda_runtime.h>

// Fixed shape: depthin (1,1,480,640) float32 -> scalar float32.
#define ROWS 480
#define COLS 640
#define TH   16
#define TW   32
#define NT   (TH * TW)    // 512
#define S    7
#define P    3
#define SMH  (TH + 2*P)   // 22
#define SMW  (TW + 2*P)   // 38
#define NBX  (COLS / TW)  // 20
#define NBY  (ROWS / TH)  // 30
#define NB   (NBX * NBY)  // 600

__device__ float g_blocksums[NB];
__device__ unsigned int g_count = 0;

__device__ __forceinline__ float fsqrt_approx(float x) {
    float r;
    asm("sqrt.approx.f32 %0, %1;" : "=f"(r) : "f"(x));
    return r;
}

__global__ __launch_bounds__(NT)
void stdev_fused_kernel(const float* __restrict__ depth, float* __restrict__ out) {
    // Tile of (z, q) per pixel, q = z^2 * (1 + cs^2 + rs^2) = |p|^2.
    __shared__ __align__(16) float2 sz[SMH][SMW];
    __shared__ float wsum[NT / 32];
    __shared__ int   is_last;

    const float inv_fx = (float)(1.0 / 582.6244816773795);
    const float inv_fy = (float)(1.0 / 582.6910327098864);
    const float cx = 313.0447587080473f;
    const float cy = 238.44389626620386f;

    const int bj0 = blockIdx.x * TW;
    const int bi0 = blockIdx.y * TH;
    const int tid = threadIdx.y * TW + threadIdx.x;
    const int bid = blockIdx.y * NBX + blockIdx.x;

    // Build (z, q) tile with +/-3 halo. Clamped halo cells are never indexed
    // by any clamped window, so their value is irrelevant but well-defined.
    #pragma unroll
    for (int idx = tid; idx < SMH * SMW; idx += NT) {
        int lr = idx / SMW, lc = idx % SMW;
        int gr = min(max(bi0 + lr - P, 0), ROWS - 1);
        int gc = min(max(bj0 + lc - P, 0), COLS - 1);
        float d = __ldg(&depth[gr * COLS + gc]);
        float z = (d > 0.0f && d < 1.01f) ? d * 1e-3f : 0.0f;
        float cs = ((float)gc - cx) * inv_fx;
        float rs = ((float)gr - cy) * inv_fy;
        float k  = fmaf(cs, cs, fmaf(rs, rs, 1.0f));
        sz[lr][lc] = make_float2(z, z * z * k);
    }
    __syncthreads();

    const int i = bi0 + threadIdx.y;
    const int j = bj0 + threadIdx.x;

    // Clamped window start (reproduces reference idif/jdif boundary shift).
    const int istart = min(max(i - P, 0), ROWS - S);
    const int jstart = min(max(j - P, 0), COLS - S);
    const int smr0 = istart - bi0 + P;   // in [0, SMH-S]
    const int smc0 = jstart - bj0 + P;   // in [0, SMW-S]

    const float2 c0 = sz[threadIdx.y + P][threadIdx.x + P];
    const float z0 = c0.x;
    const float q0 = c0.y;
    const float cs0 = ((float)j - cx) * inv_fx;
    const float rs0 = ((float)i - cy) * inv_fy;
    const float x0 = z0 * cs0;
    const float y0 = z0 * rs0;

    // d^2 = q0 + qn + zn * (A_t + B_s)
    //   A_t = -2*x0*cs_{jstart+t},  B_s = -2*(y0*rs_{istart+s} + z0)
    const float m2x0 = -2.0f * x0;
    const float m2y0 = -2.0f * y0;
    float A[S];
    #pragma unroll
    for (int t = 0; t < S; t++)
        A[t] = m2x0 * (((float)(jstart + t) - cx) * inv_fx);

    float sumd = 0.0f, sumsq = 0.0f;

    #pragma unroll
    for (int s = 0; s < S; s++) {
        const float2* row = &sz[smr0 + s][smc0];
        const float rs = ((float)(istart + s) - cy) * inv_fy;
        const float B = fmaf(m2y0, rs, -2.0f * z0);

        #pragma unroll
        for (int t = 0; t < S; t++) {
            float2 zq = row[t];                      // LDS.64
            float w  = A[t] + B;
            float sq = fmaf(zq.x, w, q0 + zq.y);
            sq = fmaxf(sq, 0.0f);                    // guard cancellation (ALU pipe)
            sumsq += sq;
            sumd  += fsqrt_approx(sq);
        }
    }

    // Unbiased variance over 49 distances.
    float var = (sumsq - sumd * sumd * (1.0f / 49.0f)) * (1.0f / 48.0f);
    float dev = (z0 > 0.0f) ? sqrtf(fmaxf(var, 0.0f)) : 0.0f;

    // Deterministic block reduction.
    float v = dev;
    #pragma unroll
    for (int o = 16; o; o >>= 1) v += __shfl_xor_sync(0xffffffffu, v, o);
    if ((tid & 31) == 0) wsum[tid >> 5] = v;
    __syncthreads();

    if (tid < 16) {
        float w = wsum[tid];
        #pragma unroll
        for (int o = 8; o; o >>= 1) w += __shfl_xor_sync(0x0000ffffu, w, o, 16);
        if (tid == 0) {
            g_blocksums[bid] = w;
            __threadfence();
            unsigned int cnt = atomicAdd(&g_count, 1u);
            is_last = (cnt == NB - 1);
        }
    }
    __syncthreads();

    // Last finished block folds the fixed 600-slot array (fixed order).
    if (is_last) {
        __threadfence();
        float srun = 0.0f;
        for (int idx = tid; idx < NB; idx += NT)
            srun += ((volatile float*)g_blocksums)[idx];
        #pragma unroll
        for (int o = 16; o; o >>= 1) srun += __shfl_xor_sync(0xffffffffu, srun, o);
        if ((tid & 31) == 0) wsum[tid >> 5] = srun;
        __syncthreads();
        if (tid < 16) {
            float w = wsum[tid];
            #pragma unroll
            for (int o = 8; o; o >>= 1) w += __shfl_xor_sync(0x0000ffffu, w, o, 16);
            if (tid == 0) {
                out[0] = w * 100.0f;
                g_count = 0;   // re-arm for next graph replay
            }
        }
    }
}

extern "C" void kernel_launch(void* const* d_in, const int* in_sizes, int n_in,
                              void* d_out, int out_size) {
    const float* depth = (const float*)d_in[0];   // depthin (1,1,480,640)
    float* out = (float*)d_out;
    dim3 grid(NBX, NBY);
    dim3 block(TW, TH);
    stdev_fused_kernel<<<grid, block>>>(depth, out);
}